// round 1
// baseline (speedup 1.0000x reference)
#include <cuda_runtime.h>
#include <cuda_bf16.h>

// ---------------------------------------------------------------------------
// Scratch (device globals — no allocation in kernel_launch)
// ---------------------------------------------------------------------------
__device__ float g_h1[256 * 32 * 512];       // conv1 output [b][c][l]
__device__ float g_h2[256 * 512 * 64];       // conv2 output transposed [b][l][c]
__device__ float g_q [256 * 512 * 64];
__device__ float g_k [256 * 512 * 64];
__device__ float g_v [256 * 512 * 64];

typedef unsigned long long u64;

__device__ __forceinline__ u64 pack2(float a, float b) {
    u64 r; asm("mov.b64 %0, {%1, %2};" : "=l"(r) : "f"(a), "f"(b)); return r;
}
__device__ __forceinline__ void ffma2(u64 &d, u64 a, u64 b) {
    asm("fma.rn.f32x2 %0, %1, %2, %0;" : "+l"(d) : "l"(a), "l"(b));
}
__device__ __forceinline__ float2 unpack2(u64 v) {
    float2 f; asm("mov.b64 {%0, %1}, %2;" : "=f"(f.x), "=f"(f.y) : "l"(v)); return f;
}

// ---------------------------------------------------------------------------
// K1: conv1 (6->32, k=3, pad=1) + BN + ReLU, per-batch block
// ---------------------------------------------------------------------------
__global__ void __launch_bounds__(256) k_conv1(
    const float* __restrict__ x,  const float* __restrict__ w,
    const float* __restrict__ cb, const float* __restrict__ bg,
    const float* __restrict__ bb, const float* __restrict__ bm,
    const float* __restrict__ bv)
{
    __shared__ float xs[6 * 516];   // padded rows (16B-aligned row stride)
    __shared__ float wf[32 * 18];
    __shared__ float bf[32];
    int b = blockIdx.x, tid = threadIdx.x;

    for (int i = tid; i < 6 * 512; i += 256) {
        int c = i >> 9, l = i & 511;
        xs[c * 516 + l + 1] = x[(b * 6 + c) * 512 + l];
    }
    if (tid < 6) { xs[tid * 516] = 0.f; xs[tid * 516 + 513] = 0.f; }
    if (tid < 32) {
        float s = bg[tid] * rsqrtf(bv[tid] + 1e-5f);
        bf[tid] = cb[tid] * s + bb[tid] - bm[tid] * s;
        #pragma unroll
        for (int j = 0; j < 18; j++) wf[tid * 18 + j] = w[tid * 18 + j] * s;
    }
    __syncthreads();

    #pragma unroll 1
    for (int it = 0; it < 16; it++) {
        int p = tid + (it << 8);
        int s_ = p & 127, o = p >> 7;      // warp-uniform o, consecutive strips
        int lb = s_ << 2;
        float a0 = bf[o], a1 = a0, a2 = a0, a3 = a0;
        #pragma unroll
        for (int c = 0; c < 6; c++) {
            const float* xr = &xs[c * 516 + lb];
            float4 xa = *(const float4*)xr;
            float x4 = xr[4], x5 = xr[5];
            float w0 = wf[o * 18 + 3 * c], w1 = wf[o * 18 + 3 * c + 1], w2 = wf[o * 18 + 3 * c + 2];
            a0 = fmaf(w0, xa.x, a0); a0 = fmaf(w1, xa.y, a0); a0 = fmaf(w2, xa.z, a0);
            a1 = fmaf(w0, xa.y, a1); a1 = fmaf(w1, xa.z, a1); a1 = fmaf(w2, xa.w, a1);
            a2 = fmaf(w0, xa.z, a2); a2 = fmaf(w1, xa.w, a2); a2 = fmaf(w2, x4,   a2);
            a3 = fmaf(w0, xa.w, a3); a3 = fmaf(w1, x4,   a3); a3 = fmaf(w2, x5,   a3);
        }
        float4 r;
        r.x = fmaxf(a0, 0.f); r.y = fmaxf(a1, 0.f);
        r.z = fmaxf(a2, 0.f); r.w = fmaxf(a3, 0.f);
        *(float4*)&g_h1[(b * 32 + o) * 512 + lb] = r;
    }
}

// ---------------------------------------------------------------------------
// K2: conv2 (32->64, k=3, pad=1) + BN + ReLU -> g_h2 transposed [b][l][o]
// ---------------------------------------------------------------------------
#define SMEM_K2 ((32 * 516 + 64 * 97 + 64) * 4)

__global__ void __launch_bounds__(256) k_conv2(
    const float* __restrict__ w,  const float* __restrict__ cb,
    const float* __restrict__ bg, const float* __restrict__ bb,
    const float* __restrict__ bm, const float* __restrict__ bv)
{
    extern __shared__ float sm2[];
    float* h1s = sm2;                 // 32 x 516 (padded, zero edges)
    float* wf  = sm2 + 32 * 516;      // 64 x 97 (pad -> conflict-free)
    float* bf  = wf  + 64 * 97;       // 64
    int b = blockIdx.x, tid = threadIdx.x;

    for (int i = tid; i < 32 * 512; i += 256) {
        int c = i >> 9, l = i & 511;
        h1s[c * 516 + l + 1] = g_h1[(b * 32 + c) * 512 + l];
    }
    if (tid < 32) { h1s[tid * 516] = 0.f; h1s[tid * 516 + 513] = 0.f; }
    for (int i = tid; i < 64 * 96; i += 256) {
        int o = i / 96, r = i % 96;
        float s = bg[o] * rsqrtf(bv[o] + 1e-5f);
        wf[o * 97 + r] = w[i] * s;
    }
    if (tid < 64) {
        float s = bg[tid] * rsqrtf(bv[tid] + 1e-5f);
        bf[tid] = cb[tid] * s + bb[tid] - bm[tid] * s;
    }
    __syncthreads();

    #pragma unroll 1
    for (int it = 0; it < 8; it++) {
        int p = tid + (it << 8);
        int o = p & 63, strip = p >> 6;   // o lane-varying, strip warp-uniform
        int lb = strip << 4;
        float bfo = bf[o];
        float acc[16];
        #pragma unroll
        for (int i = 0; i < 16; i++) acc[i] = bfo;

        #pragma unroll 4
        for (int c = 0; c < 32; c++) {
            const float* xr = &h1s[c * 516 + lb];
            float xv[18];
            float4 t0 = *(const float4*)(xr);
            float4 t1 = *(const float4*)(xr + 4);
            float4 t2 = *(const float4*)(xr + 8);
            float4 t3 = *(const float4*)(xr + 12);
            xv[0]=t0.x; xv[1]=t0.y; xv[2]=t0.z; xv[3]=t0.w;
            xv[4]=t1.x; xv[5]=t1.y; xv[6]=t1.z; xv[7]=t1.w;
            xv[8]=t2.x; xv[9]=t2.y; xv[10]=t2.z; xv[11]=t2.w;
            xv[12]=t3.x; xv[13]=t3.y; xv[14]=t3.z; xv[15]=t3.w;
            xv[16]=xr[16]; xv[17]=xr[17];
            float w0 = wf[o * 97 + 3 * c], w1 = wf[o * 97 + 3 * c + 1], w2 = wf[o * 97 + 3 * c + 2];
            #pragma unroll
            for (int i = 0; i < 16; i++) {
                acc[i] = fmaf(w0, xv[i],     acc[i]);
                acc[i] = fmaf(w1, xv[i + 1], acc[i]);
                acc[i] = fmaf(w2, xv[i + 2], acc[i]);
            }
        }
        #pragma unroll
        for (int i = 0; i < 16; i++)
            g_h2[((b << 9) + lb + i) * 64 + o] = fmaxf(acc[i], 0.f);
    }
}

// ---------------------------------------------------------------------------
// K3: QKV per-batch GEMM  [512,64] x [64,192] with packed f32x2 FMA
// ---------------------------------------------------------------------------
#define SMEM_K3 ((64 * 192 + 192 + 64 * 64) * 4)

__global__ void __launch_bounds__(256) k_qkv(
    const float* __restrict__ wq, const float* __restrict__ bq,
    const float* __restrict__ wk, const float* __restrict__ bk,
    const float* __restrict__ wv, const float* __restrict__ bv)
{
    extern __shared__ float sm3[];
    float* Ws = sm3;                  // [d][j] : 64 x 192
    float* bs = sm3 + 64 * 192;       // 192
    float* hs = bs + 192;             // 64 x 64 tile of h2
    int b = blockIdx.x, tid = threadIdx.x;

    for (int i = tid; i < 64 * 192; i += 256) {
        int d = i / 192, j = i % 192;
        float val = (j < 64) ? wq[j * 64 + d]
                  : (j < 128) ? wk[(j - 64) * 64 + d]
                              : wv[(j - 128) * 64 + d];
        Ws[i] = val;
    }
    if (tid < 192)
        bs[tid] = (tid < 64) ? bq[tid] : (tid < 128) ? bk[tid - 64] : bv[tid - 128];

    #pragma unroll 1
    for (int lt = 0; lt < 8; lt++) {
        __syncthreads();
        for (int i = tid; i < 4096; i += 256)
            hs[i] = g_h2[(b * 512 + lt * 64) * 64 + i];
        __syncthreads();

        for (int p = tid; p < 384; p += 256) {
            int jg = p % 24, ls = p / 24;
            int j0 = jg * 8, l0 = ls * 4;
            u64 acc[4][4];
            #pragma unroll
            for (int t = 0; t < 4; t++) {
                u64 bp = pack2(bs[j0 + 2 * t], bs[j0 + 2 * t + 1]);
                #pragma unroll
                for (int i = 0; i < 4; i++) acc[i][t] = bp;
            }
            #pragma unroll 4
            for (int d = 0; d < 64; d++) {
                ulonglong2 wA = *(const ulonglong2*)&Ws[d * 192 + j0];
                ulonglong2 wB = *(const ulonglong2*)&Ws[d * 192 + j0 + 4];
                #pragma unroll
                for (int i = 0; i < 4; i++) {
                    float h = hs[(l0 + i) * 64 + d];
                    u64 hh = pack2(h, h);
                    ffma2(acc[i][0], hh, wA.x);
                    ffma2(acc[i][1], hh, wA.y);
                    ffma2(acc[i][2], hh, wB.x);
                    ffma2(acc[i][3], hh, wB.y);
                }
            }
            float* outp = (j0 < 64) ? g_q : (j0 < 128) ? g_k : g_v;
            int jo = j0 & 63;
            #pragma unroll
            for (int i = 0; i < 4; i++) {
                int row = b * 512 + lt * 64 + l0 + i;
                float2* op = (float2*)&outp[row * 64 + jo];
                #pragma unroll
                for (int t = 0; t < 4; t++) op[t] = unpack2(acc[i][t]);
            }
        }
    }
}

// ---------------------------------------------------------------------------
// K4: attention + mean-pool + FC, one block per batch.
// pooled = (colsum(softmax(QK^T/8))/512) @ V  ;  out = pooled @ fc_w^T + fc_b
// ---------------------------------------------------------------------------
#define SMEM_K4 ((64 * 512 + 16 * 64 + 512 + 512) * 4)

__global__ void __launch_bounds__(512) k_attn(
    const float* __restrict__ fcw, const float* __restrict__ fcb,
    float* __restrict__ out)
{
    extern __shared__ float sm4[];
    float* Ks   = sm4;                 // [d][k] : 64 x 512
    float* qrow = sm4 + 64 * 512;      // 16 warps x 64
    float* wsum = qrow + 16 * 64;      // 512 column sums
    float* pacc = wsum + 512;          // 8 x 64 partial pooled
    __shared__ float pooled[64];

    int b = blockIdx.x, tid = threadIdx.x;
    int warp = tid >> 5, lane = tid & 31;

    wsum[tid & 511] = 0.f;

    // Load K^T into SMEM [d][k]: lane = k, conflict-free STS, L1-served LDG
    {
        int kk = tid;   // 512 threads <-> 512 keys
        const float* kr = &g_k[(b * 512 + kk) * 64];
        #pragma unroll
        for (int d0 = 0; d0 < 64; d0 += 4) {
            float4 t = *(const float4*)&kr[d0];
            Ks[(d0 + 0) * 512 + kk] = t.x;
            Ks[(d0 + 1) * 512 + kk] = t.y;
            Ks[(d0 + 2) * 512 + kk] = t.z;
            Ks[(d0 + 3) * 512 + kk] = t.w;
        }
    }
    __syncthreads();

    float accw[16];
    #pragma unroll
    for (int i = 0; i < 16; i++) accw[i] = 0.f;
    float* qr = &qrow[warp * 64];

    #pragma unroll 1
    for (int r = 0; r < 32; r++) {
        int qi = (r << 4) + warp;
        float2 qv = *(const float2*)&g_q[(b * 512 + qi) * 64 + (lane << 1)];
        *(float2*)&qr[lane << 1] = qv;
        __syncwarp();

        u64 acc[8];
        #pragma unroll
        for (int i = 0; i < 8; i++) acc[i] = 0ull;

        #pragma unroll 8
        for (int d = 0; d < 64; d++) {
            float qd = qr[d];
            u64 qq = pack2(qd, qd);
            const ulonglong2* row = (const ulonglong2*)&Ks[d * 512];
            ulonglong2 c0 = row[lane];
            ulonglong2 c1 = row[lane + 32];
            ulonglong2 c2 = row[lane + 64];
            ulonglong2 c3 = row[lane + 96];
            ffma2(acc[0], qq, c0.x); ffma2(acc[1], qq, c0.y);
            ffma2(acc[2], qq, c1.x); ffma2(acc[3], qq, c1.y);
            ffma2(acc[4], qq, c2.x); ffma2(acc[5], qq, c2.y);
            ffma2(acc[6], qq, c3.x); ffma2(acc[7], qq, c3.y);
        }

        // softmax row (scores tiny by construction -> exp safe without max)
        float e[16]; float rs = 0.f;
        #pragma unroll
        for (int i = 0; i < 8; i++) {
            float2 f = unpack2(acc[i]);
            e[2 * i]     = __expf(f.x * 0.125f);
            e[2 * i + 1] = __expf(f.y * 0.125f);
            rs += e[2 * i] + e[2 * i + 1];
        }
        #pragma unroll
        for (int off = 16; off > 0; off >>= 1)
            rs += __shfl_xor_sync(0xffffffffu, rs, off);
        float inv = 1.0f / rs;
        #pragma unroll
        for (int i = 0; i < 16; i++) accw[i] = fmaf(e[i], inv, accw[i]);
        __syncwarp();  // protect qr before next row's restage
    }

    // column-sum register accumulators -> shared (e[4j+t] <-> k = 4*(lane+32j)+t)
    #pragma unroll
    for (int j = 0; j < 4; j++) {
        int kk = 4 * (lane + 32 * j);
        #pragma unroll
        for (int t = 0; t < 4; t++)
            atomicAdd(&wsum[kk + t], accw[4 * j + t]);
    }
    __syncthreads();

    // pooled = (wsum/512) @ V
    {
        int g = tid >> 6, j = tid & 63;
        float a = 0.f;
        const float* vb = &g_v[(b * 512 + g * 64) * 64];
        #pragma unroll 8
        for (int rr = 0; rr < 64; rr++)
            a = fmaf(wsum[g * 64 + rr], vb[rr * 64 + j], a);
        pacc[tid] = a;
    }
    __syncthreads();
    if (tid < 64) {
        float s = 0.f;
        #pragma unroll
        for (int g = 0; g < 8; g++) s += pacc[g * 64 + tid];
        pooled[tid] = s * (1.0f / 512.0f);
    }
    __syncthreads();
    if (tid < 10) {
        float s = fcb[tid];
        #pragma unroll
        for (int j = 0; j < 64; j++) s = fmaf(fcw[tid * 64 + j], pooled[j], s);
        out[b * 10 + tid] = s;
    }
}

// ---------------------------------------------------------------------------
// launch
// ---------------------------------------------------------------------------
extern "C" void kernel_launch(void* const* d_in, const int* in_sizes, int n_in,
                              void* d_out, int out_size)
{
    const float* x    = (const float*)d_in[0];
    const float* c1w  = (const float*)d_in[1];
    const float* c1b  = (const float*)d_in[2];
    const float* bn1g = (const float*)d_in[3];
    const float* bn1b = (const float*)d_in[4];
    const float* bn1m = (const float*)d_in[5];
    const float* bn1v = (const float*)d_in[6];
    const float* c2w  = (const float*)d_in[7];
    const float* c2b  = (const float*)d_in[8];
    const float* bn2g = (const float*)d_in[9];
    const float* bn2b = (const float*)d_in[10];
    const float* bn2m = (const float*)d_in[11];
    const float* bn2v = (const float*)d_in[12];
    const float* wq   = (const float*)d_in[13];
    const float* bq   = (const float*)d_in[14];
    const float* wk   = (const float*)d_in[15];
    const float* bk   = (const float*)d_in[16];
    const float* wv   = (const float*)d_in[17];
    const float* bv   = (const float*)d_in[18];
    const float* fcw  = (const float*)d_in[19];
    const float* fcb  = (const float*)d_in[20];
    float* out = (float*)d_out;

    cudaFuncSetAttribute(k_conv2, cudaFuncAttributeMaxDynamicSharedMemorySize, SMEM_K2);
    cudaFuncSetAttribute(k_qkv,   cudaFuncAttributeMaxDynamicSharedMemorySize, SMEM_K3);
    cudaFuncSetAttribute(k_attn,  cudaFuncAttributeMaxDynamicSharedMemorySize, SMEM_K4);

    k_conv1<<<256, 256>>>(x, c1w, c1b, bn1g, bn1b, bn1m, bn1v);
    k_conv2<<<256, 256, SMEM_K2>>>(c2w, c2b, bn2g, bn2b, bn2m, bn2v);
    k_qkv  <<<256, 256, SMEM_K3>>>(wq, bq, wk, bk, wv, bv);
    k_attn <<<256, 512, SMEM_K4>>>(fcw, fcb, out);
}

// round 2
// speedup vs baseline: 1.5297x; 1.5297x over previous
#include <cuda_runtime.h>
#include <cuda_bf16.h>

// ---------------------------------------------------------------------------
// Scratch (device globals — no allocation in kernel_launch)
// ---------------------------------------------------------------------------
__device__ float g_h1[256 * 32 * 512];       // conv1 output [b][c][l]
__device__ float g_h2[256 * 512 * 64];       // conv2 output transposed [b][l][c]
__device__ float g_q [256 * 512 * 64];
__device__ float g_k [256 * 512 * 64];
__device__ float g_v [256 * 512 * 64];
__device__ float g_pool[256 * 64];           // pooled accumulator (atomic)

typedef unsigned long long u64;

__device__ __forceinline__ u64 pack2(float a, float b) {
    u64 r; asm("mov.b64 %0, {%1, %2};" : "=l"(r) : "f"(a), "f"(b)); return r;
}
__device__ __forceinline__ void ffma2(u64 &d, u64 a, u64 b) {
    asm("fma.rn.f32x2 %0, %1, %2, %0;" : "+l"(d) : "l"(a), "l"(b));
}
__device__ __forceinline__ float2 unpack2(u64 v) {
    float2 f; asm("mov.b64 {%0, %1}, %2;" : "=f"(f.x), "=f"(f.y) : "l"(v)); return f;
}

// ---------------------------------------------------------------------------
// K1: conv1 (6->32, k=3, pad=1) + BN + ReLU, per-batch block (+ zero g_pool)
// ---------------------------------------------------------------------------
__global__ void __launch_bounds__(256) k_conv1(
    const float* __restrict__ x,  const float* __restrict__ w,
    const float* __restrict__ cb, const float* __restrict__ bg,
    const float* __restrict__ bb, const float* __restrict__ bm,
    const float* __restrict__ bv)
{
    __shared__ float xs[6 * 516];
    __shared__ float wf[32 * 18];
    __shared__ float bf[32];
    int b = blockIdx.x, tid = threadIdx.x;

    if (tid < 64) g_pool[b * 64 + tid] = 0.f;   // zero pooled accumulator

    for (int i = tid; i < 6 * 512; i += 256) {
        int c = i >> 9, l = i & 511;
        xs[c * 516 + l + 1] = x[(b * 6 + c) * 512 + l];
    }
    if (tid < 6) { xs[tid * 516] = 0.f; xs[tid * 516 + 513] = 0.f; }
    if (tid < 32) {
        float s = bg[tid] * rsqrtf(bv[tid] + 1e-5f);
        bf[tid] = cb[tid] * s + bb[tid] - bm[tid] * s;
        #pragma unroll
        for (int j = 0; j < 18; j++) wf[tid * 18 + j] = w[tid * 18 + j] * s;
    }
    __syncthreads();

    #pragma unroll 1
    for (int it = 0; it < 16; it++) {
        int p = tid + (it << 8);
        int s_ = p & 127, o = p >> 7;
        int lb = s_ << 2;
        float a0 = bf[o], a1 = a0, a2 = a0, a3 = a0;
        #pragma unroll
        for (int c = 0; c < 6; c++) {
            const float* xr = &xs[c * 516 + lb];
            float4 xa = *(const float4*)xr;
            float x4 = xr[4], x5 = xr[5];
            float w0 = wf[o * 18 + 3 * c], w1 = wf[o * 18 + 3 * c + 1], w2 = wf[o * 18 + 3 * c + 2];
            a0 = fmaf(w0, xa.x, a0); a0 = fmaf(w1, xa.y, a0); a0 = fmaf(w2, xa.z, a0);
            a1 = fmaf(w0, xa.y, a1); a1 = fmaf(w1, xa.z, a1); a1 = fmaf(w2, xa.w, a1);
            a2 = fmaf(w0, xa.z, a2); a2 = fmaf(w1, xa.w, a2); a2 = fmaf(w2, x4,   a2);
            a3 = fmaf(w0, xa.w, a3); a3 = fmaf(w1, x4,   a3); a3 = fmaf(w2, x5,   a3);
        }
        float4 r;
        r.x = fmaxf(a0, 0.f); r.y = fmaxf(a1, 0.f);
        r.z = fmaxf(a2, 0.f); r.w = fmaxf(a3, 0.f);
        *(float4*)&g_h1[(b * 32 + o) * 512 + lb] = r;
    }
}

// ---------------------------------------------------------------------------
// K2: conv2 (32->64, k=3, pad=1) + BN + ReLU -> g_h2 [b][l][o], f32x2 math
// ---------------------------------------------------------------------------
#define SMEM_K2 ((32 * 516 + 64 * 97 + 64) * 4)

__global__ void __launch_bounds__(256) k_conv2(
    const float* __restrict__ w,  const float* __restrict__ cb,
    const float* __restrict__ bg, const float* __restrict__ bb,
    const float* __restrict__ bm, const float* __restrict__ bv)
{
    extern __shared__ float sm2[];
    float* h1s = sm2;                 // 32 x 516
    float* wf  = sm2 + 32 * 516;      // 64 x 97
    float* bf  = wf  + 64 * 97;       // 64
    int b = blockIdx.x, tid = threadIdx.x;

    for (int i = tid; i < 32 * 512; i += 256) {
        int c = i >> 9, l = i & 511;
        h1s[c * 516 + l + 1] = g_h1[(b * 32 + c) * 512 + l];
    }
    if (tid < 32) { h1s[tid * 516] = 0.f; h1s[tid * 516 + 513] = 0.f; }
    for (int i = tid; i < 64 * 96; i += 256) {
        int o = i / 96, r = i % 96;
        float s = bg[o] * rsqrtf(bv[o] + 1e-5f);
        wf[o * 97 + r] = w[i] * s;
    }
    if (tid < 64) {
        float s = bg[tid] * rsqrtf(bv[tid] + 1e-5f);
        bf[tid] = cb[tid] * s + bb[tid] - bm[tid] * s;
    }
    __syncthreads();

    #pragma unroll 1
    for (int it = 0; it < 8; it++) {
        int p = tid + (it << 8);
        int o = p & 63, strip = p >> 6;
        int lb = strip << 4;
        float bfo = bf[o];
        u64 acc2[8];
        u64 bp = pack2(bfo, bfo);
        #pragma unroll
        for (int j = 0; j < 8; j++) acc2[j] = bp;

        #pragma unroll 4
        for (int c = 0; c < 32; c++) {
            const float* xr = &h1s[c * 516 + lb];
            float xv[18];
            float4 t0 = *(const float4*)(xr);
            float4 t1 = *(const float4*)(xr + 4);
            float4 t2 = *(const float4*)(xr + 8);
            float4 t3 = *(const float4*)(xr + 12);
            xv[0]=t0.x; xv[1]=t0.y; xv[2]=t0.z; xv[3]=t0.w;
            xv[4]=t1.x; xv[5]=t1.y; xv[6]=t1.z; xv[7]=t1.w;
            xv[8]=t2.x; xv[9]=t2.y; xv[10]=t2.z; xv[11]=t2.w;
            xv[12]=t3.x; xv[13]=t3.y; xv[14]=t3.z; xv[15]=t3.w;
            xv[16]=xr[16]; xv[17]=xr[17];
            u64 xp[17];
            #pragma unroll
            for (int i = 0; i < 17; i++) xp[i] = pack2(xv[i], xv[i + 1]);
            float w0 = wf[o * 97 + 3 * c], w1 = wf[o * 97 + 3 * c + 1], w2 = wf[o * 97 + 3 * c + 2];
            u64 w0p = pack2(w0, w0), w1p = pack2(w1, w1), w2p = pack2(w2, w2);
            #pragma unroll
            for (int j = 0; j < 8; j++) {
                ffma2(acc2[j], w0p, xp[2 * j]);
                ffma2(acc2[j], w1p, xp[2 * j + 1]);
                ffma2(acc2[j], w2p, xp[2 * j + 2]);
            }
        }
        #pragma unroll
        for (int j = 0; j < 8; j++) {
            float2 f = unpack2(acc2[j]);
            g_h2[((b << 9) + lb + 2 * j)     * 64 + o] = fmaxf(f.x, 0.f);
            g_h2[((b << 9) + lb + 2 * j + 1) * 64 + o] = fmaxf(f.y, 0.f);
        }
    }
}

// ---------------------------------------------------------------------------
// K3: QKV per-batch GEMM  [512,64] x [64,192] with packed f32x2 FMA
// ---------------------------------------------------------------------------
#define SMEM_K3 ((64 * 192 + 192 + 64 * 64) * 4)

__global__ void __launch_bounds__(256) k_qkv(
    const float* __restrict__ wq, const float* __restrict__ bq,
    const float* __restrict__ wk, const float* __restrict__ bk,
    const float* __restrict__ wv, const float* __restrict__ bv)
{
    extern __shared__ float sm3[];
    float* Ws = sm3;                  // [d][j] : 64 x 192
    float* bs = sm3 + 64 * 192;       // 192
    float* hs = bs + 192;             // 64 x 64 tile of h2
    int b = blockIdx.x, tid = threadIdx.x;

    for (int i = tid; i < 64 * 192; i += 256) {
        int d = i / 192, j = i % 192;
        float val = (j < 64) ? wq[j * 64 + d]
                  : (j < 128) ? wk[(j - 64) * 64 + d]
                              : wv[(j - 128) * 64 + d];
        Ws[i] = val;
    }
    if (tid < 192)
        bs[tid] = (tid < 64) ? bq[tid] : (tid < 128) ? bk[tid - 64] : bv[tid - 128];

    #pragma unroll 1
    for (int lt = 0; lt < 8; lt++) {
        __syncthreads();
        for (int i = tid; i < 4096; i += 256)
            hs[i] = g_h2[(b * 512 + lt * 64) * 64 + i];
        __syncthreads();

        for (int p = tid; p < 384; p += 256) {
            int jg = p % 24, ls = p / 24;
            int j0 = jg * 8, l0 = ls * 4;
            u64 acc[4][4];
            #pragma unroll
            for (int t = 0; t < 4; t++) {
                u64 bp = pack2(bs[j0 + 2 * t], bs[j0 + 2 * t + 1]);
                #pragma unroll
                for (int i = 0; i < 4; i++) acc[i][t] = bp;
            }
            #pragma unroll 4
            for (int d = 0; d < 64; d++) {
                ulonglong2 wA = *(const ulonglong2*)&Ws[d * 192 + j0];
                ulonglong2 wB = *(const ulonglong2*)&Ws[d * 192 + j0 + 4];
                #pragma unroll
                for (int i = 0; i < 4; i++) {
                    float h = hs[(l0 + i) * 64 + d];
                    u64 hh = pack2(h, h);
                    ffma2(acc[i][0], hh, wA.x);
                    ffma2(acc[i][1], hh, wA.y);
                    ffma2(acc[i][2], hh, wB.x);
                    ffma2(acc[i][3], hh, wB.y);
                }
            }
            float* outp = (j0 < 64) ? g_q : (j0 < 128) ? g_k : g_v;
            int jo = j0 & 63;
            #pragma unroll
            for (int i = 0; i < 4; i++) {
                int row = b * 512 + lt * 64 + l0 + i;
                float2* op = (float2*)&outp[row * 64 + jo];
                #pragma unroll
                for (int t = 0; t < 4; t++) op[t] = unpack2(acc[i][t]);
            }
        }
    }
}

// ---------------------------------------------------------------------------
// K4: attention colsum + partial pool. 1024 blocks = 256 batches x 4 quarters.
// 256 threads = 8 warps; each warp register-blocks 8 q-rows over full 512-k
// row (64 u64 f32x2 accumulators) so each K LDS read feeds 8 rows.
// ---------------------------------------------------------------------------
#define SMEM_K4 ((64 * 512 + 8 * 8 * 64 + 512) * 4)

__global__ void __launch_bounds__(256) k_attn(void)
{
    extern __shared__ float sm4[];
    float* Ks   = sm4;                 // [d][k] : 64 x 512
    float* qs   = sm4 + 64 * 512;      // 8 warps x 8 rows x 64
    float* wsum = qs + 8 * 8 * 64;     // 512 column sums (this block's rows)

    int blk = blockIdx.x;
    int b = blk >> 2, qtr = blk & 3;
    int tid = threadIdx.x, warp = tid >> 5, lane = tid & 31;

    wsum[tid] = 0.f; wsum[tid + 256] = 0.f;

    // Load K^T into SMEM [d][k] (conflict-free STS; L2-hit LDG, reused 4x)
    for (int kk = tid; kk < 512; kk += 256) {
        const float* kr = &g_k[(b * 512 + kk) * 64];
        #pragma unroll
        for (int d0 = 0; d0 < 64; d0 += 4) {
            float4 t = *(const float4*)&kr[d0];
            Ks[(d0 + 0) * 512 + kk] = t.x;
            Ks[(d0 + 1) * 512 + kk] = t.y;
            Ks[(d0 + 2) * 512 + kk] = t.z;
            Ks[(d0 + 3) * 512 + kk] = t.w;
        }
    }
    __syncthreads();

    float accw[16];
    #pragma unroll
    for (int i = 0; i < 16; i++) accw[i] = 0.f;

    float* q = &qs[warp * 512];

    #pragma unroll 1
    for (int pass = 0; pass < 2; pass++) {
        int row0 = qtr * 128 + warp * 16 + pass * 8;

        __syncwarp();
        #pragma unroll
        for (int r = 0; r < 8; r++) {
            float2 v = *(const float2*)&g_q[(b * 512 + row0 + r) * 64 + (lane << 1)];
            *(float2*)&q[r * 64 + (lane << 1)] = v;
        }
        __syncwarp();

        u64 acc[8][8];
        #pragma unroll
        for (int r = 0; r < 8; r++)
            #pragma unroll
            for (int j = 0; j < 8; j++) acc[r][j] = 0ull;

        #pragma unroll 2
        for (int d = 0; d < 64; d++) {
            const ulonglong2* kr = (const ulonglong2*)&Ks[d * 512];
            ulonglong2 c0 = kr[lane];
            ulonglong2 c1 = kr[lane + 32];
            ulonglong2 c2 = kr[lane + 64];
            ulonglong2 c3 = kr[lane + 96];
            #pragma unroll
            for (int r = 0; r < 8; r++) {
                float qd = q[r * 64 + d];       // LDS broadcast
                u64 qq = pack2(qd, qd);
                ffma2(acc[r][0], qq, c0.x); ffma2(acc[r][1], qq, c0.y);
                ffma2(acc[r][2], qq, c1.x); ffma2(acc[r][3], qq, c1.y);
                ffma2(acc[r][4], qq, c2.x); ffma2(acc[r][5], qq, c2.y);
                ffma2(acc[r][6], qq, c3.x); ffma2(acc[r][7], qq, c3.y);
            }
        }

        // softmax per row (scores tiny -> exp safe without max), colsum accum
        #pragma unroll
        for (int r = 0; r < 8; r++) {
            float e[16]; float rs = 0.f;
            #pragma unroll
            for (int j = 0; j < 8; j++) {
                float2 f = unpack2(acc[r][j]);
                e[2 * j]     = __expf(f.x * 0.125f);
                e[2 * j + 1] = __expf(f.y * 0.125f);
                rs += e[2 * j] + e[2 * j + 1];
            }
            #pragma unroll
            for (int off = 16; off > 0; off >>= 1)
                rs += __shfl_xor_sync(0xffffffffu, rs, off);
            float inv = 1.0f / rs;
            #pragma unroll
            for (int i = 0; i < 16; i++) accw[i] = fmaf(e[i], inv, accw[i]);
        }
    }

    // column sums -> shared (i <-> k = 4*(lane+32*(i>>2)) + (i&3))
    #pragma unroll
    for (int m = 0; m < 4; m++) {
        int kk = 4 * (lane + 32 * m);
        #pragma unroll
        for (int t = 0; t < 4; t++)
            atomicAdd(&wsum[kk + t], accw[4 * m + t]);
    }
    __syncthreads();

    // partial pooled: (this block's wsum) @ V, atomically into g_pool
    {
        int g = tid >> 6, j = tid & 63;             // 4 k-chunks x 64 dims
        float a = 0.f;
        const float* vb = &g_v[(b * 512 + g * 128) * 64];
        #pragma unroll 8
        for (int rr = 0; rr < 128; rr++)
            a = fmaf(wsum[g * 128 + rr], vb[rr * 64 + j], a);
        atomicAdd(&g_pool[b * 64 + j], a);
    }
}

// ---------------------------------------------------------------------------
// K5: final FC  out[b][c] = fcb[c] + (pool[b]/512) . fcw[c]
// ---------------------------------------------------------------------------
__global__ void __launch_bounds__(256) k_fc(
    const float* __restrict__ fcw, const float* __restrict__ fcb,
    float* __restrict__ out)
{
    int idx = blockIdx.x * 256 + threadIdx.x;
    if (idx >= 256 * 10) return;
    int b = idx / 10, c = idx % 10;
    float s = 0.f;
    const float* pw = &g_pool[b * 64];
    const float* wr = &fcw[c * 64];
    #pragma unroll
    for (int j = 0; j < 64; j++) s = fmaf(wr[j], pw[j], s);
    out[idx] = fmaf(s, 1.0f / 512.0f, fcb[c]);
}

// ---------------------------------------------------------------------------
// launch
// ---------------------------------------------------------------------------
extern "C" void kernel_launch(void* const* d_in, const int* in_sizes, int n_in,
                              void* d_out, int out_size)
{
    const float* x    = (const float*)d_in[0];
    const float* c1w  = (const float*)d_in[1];
    const float* c1b  = (const float*)d_in[2];
    const float* bn1g = (const float*)d_in[3];
    const float* bn1b = (const float*)d_in[4];
    const float* bn1m = (const float*)d_in[5];
    const float* bn1v = (const float*)d_in[6];
    const float* c2w  = (const float*)d_in[7];
    const float* c2b  = (const float*)d_in[8];
    const float* bn2g = (const float*)d_in[9];
    const float* bn2b = (const float*)d_in[10];
    const float* bn2m = (const float*)d_in[11];
    const float* bn2v = (const float*)d_in[12];
    const float* wq   = (const float*)d_in[13];
    const float* bq   = (const float*)d_in[14];
    const float* wk   = (const float*)d_in[15];
    const float* bk   = (const float*)d_in[16];
    const float* wv   = (const float*)d_in[17];
    const float* bv   = (const float*)d_in[18];
    const float* fcw  = (const float*)d_in[19];
    const float* fcb  = (const float*)d_in[20];
    float* out = (float*)d_out;

    cudaFuncSetAttribute(k_conv2, cudaFuncAttributeMaxDynamicSharedMemorySize, SMEM_K2);
    cudaFuncSetAttribute(k_qkv,   cudaFuncAttributeMaxDynamicSharedMemorySize, SMEM_K3);
    cudaFuncSetAttribute(k_attn,  cudaFuncAttributeMaxDynamicSharedMemorySize, SMEM_K4);

    k_conv1<<<256, 256>>>(x, c1w, c1b, bn1g, bn1b, bn1m, bn1v);
    k_conv2<<<256, 256, SMEM_K2>>>(c2w, c2b, bn2g, bn2b, bn2m, bn2v);
    k_qkv  <<<256, 256, SMEM_K3>>>(wq, bq, wk, bk, wv, bv);
    k_attn <<<1024, 256, SMEM_K4>>>();
    k_fc   <<<10, 256>>>(fcw, fcb, out);
}

// round 3
// speedup vs baseline: 1.5619x; 1.0211x over previous
#include <cuda_runtime.h>
#include <cuda_bf16.h>

// ---------------------------------------------------------------------------
// Scratch (device globals — no allocation in kernel_launch)
// ---------------------------------------------------------------------------
__device__ float g_h1[256 * 32 * 512];       // conv1 output [b][c][l]
__device__ float g_h2[256 * 512 * 64];       // conv2 output transposed [b][l][c]
__device__ float g_q [256 * 512 * 64];
__device__ float g_k [256 * 512 * 64];
__device__ float g_v [256 * 512 * 64];
__device__ float g_pool[256 * 64];           // pooled accumulator (atomic)

typedef unsigned long long u64;

__device__ __forceinline__ u64 pack2(float a, float b) {
    u64 r; asm("mov.b64 %0, {%1, %2};" : "=l"(r) : "f"(a), "f"(b)); return r;
}
__device__ __forceinline__ void ffma2(u64 &d, u64 a, u64 b) {
    asm("fma.rn.f32x2 %0, %1, %2, %0;" : "+l"(d) : "l"(a), "l"(b));
}
__device__ __forceinline__ float2 unpack2(u64 v) {
    float2 f; asm("mov.b64 {%0, %1}, %2;" : "=f"(f.x), "=f"(f.y) : "l"(v)); return f;
}

// ---------------------------------------------------------------------------
// K1: conv1 (6->32, k=3, pad=1) + BN + ReLU. 512 blocks = 256 b x 2 L-halves.
// ---------------------------------------------------------------------------
__global__ void __launch_bounds__(256) k_conv1(
    const float* __restrict__ x,  const float* __restrict__ w,
    const float* __restrict__ cb, const float* __restrict__ bg,
    const float* __restrict__ bb, const float* __restrict__ bm,
    const float* __restrict__ bv)
{
    __shared__ float xs[6 * 264];   // local idx j <-> global l = L0-1+j, j in [0,258)
    __shared__ float wf[32 * 18];
    __shared__ float bf[32];
    int blk = blockIdx.x, tid = threadIdx.x;
    int b = blk >> 1, L0 = (blk & 1) << 8;

    if (tid < 64 && (blk & 1) == 0) g_pool[b * 64 + tid] = 0.f;

    for (int i = tid; i < 6 * 258; i += 256) {
        int c = i / 258, j = i % 258;
        int g = L0 - 1 + j;
        xs[c * 264 + j] = (g >= 0 && g < 512) ? x[(b * 6 + c) * 512 + g] : 0.f;
    }
    if (tid < 32) {
        float s = bg[tid] * rsqrtf(bv[tid] + 1e-5f);
        bf[tid] = cb[tid] * s + bb[tid] - bm[tid] * s;
        #pragma unroll
        for (int j = 0; j < 18; j++) wf[tid * 18 + j] = w[tid * 18 + j] * s;
    }
    __syncthreads();

    #pragma unroll 1
    for (int it = 0; it < 8; it++) {
        int p = tid + (it << 8);
        int s_ = p & 63, o = p >> 6;       // 64 strips x 32 out-channels
        int lb = s_ << 2;                  // local output base (0..252)
        float a0 = bf[o], a1 = a0, a2 = a0, a3 = a0;
        #pragma unroll
        for (int c = 0; c < 6; c++) {
            const float* xr = &xs[c * 264 + lb];
            float4 xa = *(const float4*)xr;
            float x4 = xr[4], x5 = xr[5];
            float w0 = wf[o * 18 + 3 * c], w1 = wf[o * 18 + 3 * c + 1], w2 = wf[o * 18 + 3 * c + 2];
            a0 = fmaf(w0, xa.x, a0); a0 = fmaf(w1, xa.y, a0); a0 = fmaf(w2, xa.z, a0);
            a1 = fmaf(w0, xa.y, a1); a1 = fmaf(w1, xa.z, a1); a1 = fmaf(w2, xa.w, a1);
            a2 = fmaf(w0, xa.z, a2); a2 = fmaf(w1, xa.w, a2); a2 = fmaf(w2, x4,   a2);
            a3 = fmaf(w0, xa.w, a3); a3 = fmaf(w1, x4,   a3); a3 = fmaf(w2, x5,   a3);
        }
        float4 r;
        r.x = fmaxf(a0, 0.f); r.y = fmaxf(a1, 0.f);
        r.z = fmaxf(a2, 0.f); r.w = fmaxf(a3, 0.f);
        *(float4*)&g_h1[(b * 32 + o) * 512 + L0 + lb] = r;
    }
}

// ---------------------------------------------------------------------------
// K2: conv2 (32->64, k=3, pad=1) + BN + ReLU -> g_h2 [b][l][o].
// 512 blocks = 256 b x 2 L-halves, f32x2 math.
// ---------------------------------------------------------------------------
#define SMEM_K2 ((32 * 264 + 64 * 97 + 64) * 4)

__global__ void __launch_bounds__(256) k_conv2(
    const float* __restrict__ w,  const float* __restrict__ cb,
    const float* __restrict__ bg, const float* __restrict__ bb,
    const float* __restrict__ bm, const float* __restrict__ bv)
{
    extern __shared__ float sm2[];
    float* h1s = sm2;                 // 32 x 264 (idx j <-> global L0-1+j)
    float* wf  = sm2 + 32 * 264;      // 64 x 97
    float* bf  = wf  + 64 * 97;       // 64
    int blk = blockIdx.x, tid = threadIdx.x;
    int b = blk >> 1, L0 = (blk & 1) << 8;

    for (int i = tid; i < 32 * 258; i += 256) {
        int c = i / 258, j = i % 258;
        int g = L0 - 1 + j;
        h1s[c * 264 + j] = (g >= 0 && g < 512) ? g_h1[(b * 32 + c) * 512 + g] : 0.f;
    }
    for (int i = tid; i < 64 * 96; i += 256) {
        int o = i / 96, r = i % 96;
        float s = bg[o] * rsqrtf(bv[o] + 1e-5f);
        wf[o * 97 + r] = w[i] * s;
    }
    if (tid < 64) {
        float s = bg[tid] * rsqrtf(bv[tid] + 1e-5f);
        bf[tid] = cb[tid] * s + bb[tid] - bm[tid] * s;
    }
    __syncthreads();

    #pragma unroll 1
    for (int it = 0; it < 4; it++) {
        int p = tid + (it << 8);
        int o = p & 63, strip = p >> 6;    // strip 0..15
        int lb = strip << 4;               // local base (0..240)
        float bfo = bf[o];
        u64 acc2[8];
        u64 bp = pack2(bfo, bfo);
        #pragma unroll
        for (int j = 0; j < 8; j++) acc2[j] = bp;

        #pragma unroll 4
        for (int c = 0; c < 32; c++) {
            const float* xr = &h1s[c * 264 + lb];
            float xv[18];
            float4 t0 = *(const float4*)(xr);
            float4 t1 = *(const float4*)(xr + 4);
            float4 t2 = *(const float4*)(xr + 8);
            float4 t3 = *(const float4*)(xr + 12);
            xv[0]=t0.x; xv[1]=t0.y; xv[2]=t0.z; xv[3]=t0.w;
            xv[4]=t1.x; xv[5]=t1.y; xv[6]=t1.z; xv[7]=t1.w;
            xv[8]=t2.x; xv[9]=t2.y; xv[10]=t2.z; xv[11]=t2.w;
            xv[12]=t3.x; xv[13]=t3.y; xv[14]=t3.z; xv[15]=t3.w;
            xv[16]=xr[16]; xv[17]=xr[17];
            u64 xp[17];
            #pragma unroll
            for (int i = 0; i < 17; i++) xp[i] = pack2(xv[i], xv[i + 1]);
            float w0 = wf[o * 97 + 3 * c], w1 = wf[o * 97 + 3 * c + 1], w2 = wf[o * 97 + 3 * c + 2];
            u64 w0p = pack2(w0, w0), w1p = pack2(w1, w1), w2p = pack2(w2, w2);
            #pragma unroll
            for (int j = 0; j < 8; j++) {
                ffma2(acc2[j], w0p, xp[2 * j]);
                ffma2(acc2[j], w1p, xp[2 * j + 1]);
                ffma2(acc2[j], w2p, xp[2 * j + 2]);
            }
        }
        #pragma unroll
        for (int j = 0; j < 8; j++) {
            float2 f = unpack2(acc2[j]);
            int lg = L0 + lb + 2 * j;
            g_h2[((b << 9) + lg)     * 64 + o] = fmaxf(f.x, 0.f);
            g_h2[((b << 9) + lg + 1) * 64 + o] = fmaxf(f.y, 0.f);
        }
    }
}

// ---------------------------------------------------------------------------
// K3: QKV GEMM [512,64] x [64,192]. 512 blocks = 256 b x 2 row-halves.
// ---------------------------------------------------------------------------
#define SMEM_K3 ((64 * 192 + 192 + 64 * 64) * 4)

__global__ void __launch_bounds__(256) k_qkv(
    const float* __restrict__ wq, const float* __restrict__ bq,
    const float* __restrict__ wk, const float* __restrict__ bk,
    const float* __restrict__ wv, const float* __restrict__ bv)
{
    extern __shared__ float sm3[];
    float* Ws = sm3;                  // [d][j] : 64 x 192
    float* bs = sm3 + 64 * 192;       // 192
    float* hs = bs + 192;             // 64 x 64 tile of h2
    int blk = blockIdx.x, tid = threadIdx.x;
    int b = blk >> 1, R0 = (blk & 1) << 8;

    for (int i = tid; i < 64 * 192; i += 256) {
        int d = i / 192, j = i % 192;
        float val = (j < 64) ? wq[j * 64 + d]
                  : (j < 128) ? wk[(j - 64) * 64 + d]
                              : wv[(j - 128) * 64 + d];
        Ws[i] = val;
    }
    if (tid < 192)
        bs[tid] = (tid < 64) ? bq[tid] : (tid < 128) ? bk[tid - 64] : bv[tid - 128];

    #pragma unroll 1
    for (int lt = 0; lt < 4; lt++) {
        __syncthreads();
        for (int i = tid; i < 4096; i += 256)
            hs[i] = g_h2[(b * 512 + R0 + lt * 64) * 64 + i];
        __syncthreads();

        for (int p = tid; p < 384; p += 256) {
            int jg = p % 24, ls = p / 24;
            int j0 = jg * 8, l0 = ls * 4;
            u64 acc[4][4];
            #pragma unroll
            for (int t = 0; t < 4; t++) {
                u64 bp = pack2(bs[j0 + 2 * t], bs[j0 + 2 * t + 1]);
                #pragma unroll
                for (int i = 0; i < 4; i++) acc[i][t] = bp;
            }
            #pragma unroll 4
            for (int d = 0; d < 64; d++) {
                ulonglong2 wA = *(const ulonglong2*)&Ws[d * 192 + j0];
                ulonglong2 wB = *(const ulonglong2*)&Ws[d * 192 + j0 + 4];
                #pragma unroll
                for (int i = 0; i < 4; i++) {
                    float h = hs[(l0 + i) * 64 + d];
                    u64 hh = pack2(h, h);
                    ffma2(acc[i][0], hh, wA.x);
                    ffma2(acc[i][1], hh, wA.y);
                    ffma2(acc[i][2], hh, wB.x);
                    ffma2(acc[i][3], hh, wB.y);
                }
            }
            float* outp = (j0 < 64) ? g_q : (j0 < 128) ? g_k : g_v;
            int jo = j0 & 63;
            #pragma unroll
            for (int i = 0; i < 4; i++) {
                int row = b * 512 + R0 + lt * 64 + l0 + i;
                float2* op = (float2*)&outp[row * 64 + jo];
                #pragma unroll
                for (int t = 0; t < 4; t++) op[t] = unpack2(acc[i][t]);
            }
        }
    }
}

// ---------------------------------------------------------------------------
// K4: attention colsum + partial pool. 1024 blocks = 256 b x 4 row-quarters.
// 512 threads = 16 warps: warp = (rowgrp 0..7, colhalf 0..1).
// Each warp: 8 q-rows x 256 k-cols in 32 u64 f32x2 accumulators.
// Row-sums combined across the two column-half warps via smem.
// ---------------------------------------------------------------------------
#define SMEM_K4 ((64 * 512 + 8 * 8 * 64 + 512 + 2 * 2 * 64) * 4)

__global__ void __launch_bounds__(512) k_attn(void)
{
    extern __shared__ float sm4[];
    float* Ks   = sm4;                  // [d][k] : 64 x 512
    float* qs   = sm4 + 64 * 512;       // [8 rowgrps][8 rows][64]
    float* wsum = qs + 8 * 8 * 64;      // [512] partial colsum for this block
    float* rsum = wsum + 512;           // [pass][half][64 rows]

    int blk = blockIdx.x;
    int b = blk >> 2, qtr = blk & 3;
    int tid = threadIdx.x, warp = tid >> 5, lane = tid & 31;
    int rowgrp = warp >> 1, half = warp & 1;
    int colbase = half << 8;

    wsum[tid] = 0.f;

    // Load K^T into SMEM [d][k] (512 threads <-> 512 keys, conflict-free STS)
    {
        const float* kr = &g_k[(b * 512 + tid) * 64];
        #pragma unroll
        for (int d0 = 0; d0 < 64; d0 += 4) {
            float4 t = *(const float4*)&kr[d0];
            Ks[(d0 + 0) * 512 + tid] = t.x;
            Ks[(d0 + 1) * 512 + tid] = t.y;
            Ks[(d0 + 2) * 512 + tid] = t.z;
            Ks[(d0 + 3) * 512 + tid] = t.w;
        }
    }
    __syncthreads();

    float accw[8];
    #pragma unroll
    for (int i = 0; i < 8; i++) accw[i] = 0.f;

    float* q = &qs[rowgrp * 512];

    #pragma unroll 1
    for (int pass = 0; pass < 2; pass++) {
        int row0 = qtr * 128 + pass * 64 + rowgrp * 8;

        // Stage q rows (both colhalf warps write identical values - benign)
        #pragma unroll
        for (int r = 0; r < 8; r++) {
            float2 v = *(const float2*)&g_q[(b * 512 + row0 + r) * 64 + (lane << 1)];
            *(float2*)&q[r * 64 + (lane << 1)] = v;
        }
        __syncwarp();

        u64 acc[8][4];
        #pragma unroll
        for (int r = 0; r < 8; r++)
            #pragma unroll
            for (int j = 0; j < 4; j++) acc[r][j] = 0ull;

        #pragma unroll 2
        for (int d = 0; d < 64; d++) {
            const ulonglong2* kr2 = (const ulonglong2*)&Ks[d * 512 + colbase];
            ulonglong2 c0 = kr2[lane];
            ulonglong2 c1 = kr2[lane + 32];
            #pragma unroll
            for (int r = 0; r < 8; r++) {
                float qd = q[r * 64 + d];       // LDS broadcast
                u64 qq = pack2(qd, qd);
                ffma2(acc[r][0], qq, c0.x);
                ffma2(acc[r][1], qq, c0.y);
                ffma2(acc[r][2], qq, c1.x);
                ffma2(acc[r][3], qq, c1.y);
            }
        }

        // exp (scores tiny by construction -> no max shift needed),
        // partial row-sums; repack e into acc to stay under reg cap.
        #pragma unroll
        for (int r = 0; r < 8; r++) {
            float rs = 0.f;
            #pragma unroll
            for (int j = 0; j < 4; j++) {
                float2 f = unpack2(acc[r][j]);
                float e0 = __expf(f.x * 0.125f);
                float e1 = __expf(f.y * 0.125f);
                rs += e0 + e1;
                acc[r][j] = pack2(e0, e1);
            }
            #pragma unroll
            for (int off = 16; off > 0; off >>= 1)
                rs += __shfl_xor_sync(0xffffffffu, rs, off);
            if (lane == 0) rsum[(pass * 2 + half) * 64 + rowgrp * 8 + r] = rs;
        }
        __syncthreads();

        // normalize with combined row-sum, accumulate column sums
        #pragma unroll
        for (int r = 0; r < 8; r++) {
            float tot = rsum[(pass * 2 + 0) * 64 + rowgrp * 8 + r]
                      + rsum[(pass * 2 + 1) * 64 + rowgrp * 8 + r];
            float inv = 1.0f / tot;
            #pragma unroll
            for (int j = 0; j < 4; j++) {
                float2 f = unpack2(acc[r][j]);
                accw[2 * j]     = fmaf(f.x, inv, accw[2 * j]);
                accw[2 * j + 1] = fmaf(f.y, inv, accw[2 * j + 1]);
            }
        }
        __syncthreads();   // protect qs/rsum before next pass restage
    }

    // colsum accumulators -> shared.
    // acc[r][0..1] <-> cols colbase + 4*lane + {0..3}
    // acc[r][2..3] <-> cols colbase + 128 + 4*lane + {0..3}
    #pragma unroll
    for (int t = 0; t < 4; t++) {
        atomicAdd(&wsum[colbase + 4 * lane + t],       accw[t]);
        atomicAdd(&wsum[colbase + 128 + 4 * lane + t], accw[4 + t]);
    }
    __syncthreads();

    // partial pooled: (this block's wsum) @ V, atomically into g_pool
    {
        int g = tid >> 6, j = tid & 63;             // 8 k-chunks x 64 dims
        float a = 0.f;
        const float* vb = &g_v[(b * 512 + g * 64) * 64];
        #pragma unroll 8
        for (int rr = 0; rr < 64; rr++)
            a = fmaf(wsum[g * 64 + rr], vb[rr * 64 + j], a);
        atomicAdd(&g_pool[b * 64 + j], a);
    }
}

// ---------------------------------------------------------------------------
// K5: final FC  out[b][c] = fcb[c] + (pool[b]/512) . fcw[c]
// ---------------------------------------------------------------------------
__global__ void __launch_bounds__(256) k_fc(
    const float* __restrict__ fcw, const float* __restrict__ fcb,
    float* __restrict__ out)
{
    int idx = blockIdx.x * 256 + threadIdx.x;
    if (idx >= 256 * 10) return;
    int b = idx / 10, c = idx % 10;
    float s = 0.f;
    const float* pw = &g_pool[b * 64];
    const float* wr = &fcw[c * 64];
    #pragma unroll
    for (int j = 0; j < 64; j++) s = fmaf(wr[j], pw[j], s);
    out[idx] = fmaf(s, 1.0f / 512.0f, fcb[c]);
}

// ---------------------------------------------------------------------------
// launch
// ---------------------------------------------------------------------------
extern "C" void kernel_launch(void* const* d_in, const int* in_sizes, int n_in,
                              void* d_out, int out_size)
{
    const float* x    = (const float*)d_in[0];
    const float* c1w  = (const float*)d_in[1];
    const float* c1b  = (const float*)d_in[2];
    const float* bn1g = (const float*)d_in[3];
    const float* bn1b = (const float*)d_in[4];
    const float* bn1m = (const float*)d_in[5];
    const float* bn1v = (const float*)d_in[6];
    const float* c2w  = (const float*)d_in[7];
    const float* c2b  = (const float*)d_in[8];
    const float* bn2g = (const float*)d_in[9];
    const float* bn2b = (const float*)d_in[10];
    const float* bn2m = (const float*)d_in[11];
    const float* bn2v = (const float*)d_in[12];
    const float* wq   = (const float*)d_in[13];
    const float* bq   = (const float*)d_in[14];
    const float* wk   = (const float*)d_in[15];
    const float* bk   = (const float*)d_in[16];
    const float* wv   = (const float*)d_in[17];
    const float* bv   = (const float*)d_in[18];
    const float* fcw  = (const float*)d_in[19];
    const float* fcb  = (const float*)d_in[20];
    float* out = (float*)d_out;

    cudaFuncSetAttribute(k_conv2, cudaFuncAttributeMaxDynamicSharedMemorySize, SMEM_K2);
    cudaFuncSetAttribute(k_qkv,   cudaFuncAttributeMaxDynamicSharedMemorySize, SMEM_K3);
    cudaFuncSetAttribute(k_attn,  cudaFuncAttributeMaxDynamicSharedMemorySize, SMEM_K4);

    k_conv1<<<512, 256>>>(x, c1w, c1b, bn1g, bn1b, bn1m, bn1v);
    k_conv2<<<512, 256, SMEM_K2>>>(c2w, c2b, bn2g, bn2b, bn2m, bn2v);
    k_qkv  <<<512, 256, SMEM_K3>>>(wq, bq, wk, bk, wv, bv);
    k_attn <<<1024, 512, SMEM_K4>>>();
    k_fc   <<<10, 256>>>(fcw, fcb, out);
}